// round 14
// baseline (speedup 1.0000x reference)
#include <cuda_runtime.h>
#include <cuda_bf16.h>
#include <cstdint>

#define Hd   768
#define Bn   4
#define DECn 128
#define ENCn 512
#define K2   1536          // stored split K (hi | lo)
#define MROWS (Bn*ENCn + Bn*DECn)   // 2560
#define NTILES 1024        // 4 b * 4 dstrips(32) * 64 enc-tiles(8)

// ---------------- scratch (__device__ globals; no allocs allowed) ----------
__device__ uint32_t       g_enc_h[Bn * ENCn * Hd / 2];   // f16x2 packed
__device__ uint32_t       g_dec_h[Bn * DECn * Hd / 2];   // f16x2 packed
__device__ __nv_bfloat16  g_in_split[MROWS * K2];
__device__ __nv_bfloat16  g_w1t[Hd * K2];
__device__ __nv_bfloat16  g_w2t[Hd * K2];

__device__ __forceinline__ uint32_t smem_u32(const void* p) {
    return (uint32_t)__cvta_generic_to_shared(p);
}
__device__ __forceinline__ void ldm_x4(uint32_t addr, uint32_t* r) {
    asm volatile("ldmatrix.sync.aligned.m8n8.x4.shared.b16 {%0,%1,%2,%3}, [%4];"
        : "=r"(r[0]), "=r"(r[1]), "=r"(r[2]), "=r"(r[3]) : "r"(addr));
}
__device__ __forceinline__ void mma16816(float* d, const uint32_t* a, const uint32_t* b) {
    asm volatile("mma.sync.aligned.m16n8k16.row.col.f32.bf16.bf16.f32 "
        "{%0,%1,%2,%3}, {%4,%5,%6,%7}, {%8,%9}, {%0,%1,%2,%3};"
        : "+f"(d[0]), "+f"(d[1]), "+f"(d[2]), "+f"(d[3])
        : "r"(a[0]), "r"(a[1]), "r"(a[2]), "r"(a[3]), "r"(b[0]), "r"(b[1]));
}
#define CP_ASYNC16(saddr, gptr) \
    asm volatile("cp.async.cg.shared.global [%0], [%1], 16;" :: "r"(saddr), "l"(gptr))
#define CP_COMMIT() asm volatile("cp.async.commit_group;" ::: "memory")
#define CP_WAIT(n)  asm volatile("cp.async.wait_group %0;" :: "n"(n) : "memory")

// ---------------------------------------------------------------------------
// prep: split inputs hi|lo; transpose+split W1/W2   (unchanged, known-good)
// ---------------------------------------------------------------------------
#define NB_SPLIT (MROWS * (Hd / 4) / 256)          // 1920
#define NB_WT    ((Hd / 32) * (Hd / 32))           // 576 per matrix

__global__ __launch_bounds__(256) void prep_kernel(
    const float* __restrict__ enc, const float* __restrict__ dec,
    const float* __restrict__ W1,  const float* __restrict__ W2,
    __nv_bfloat16* __restrict__ dst,
    __nv_bfloat16* __restrict__ D1, __nv_bfloat16* __restrict__ D2)
{
    const int bid = blockIdx.x;
    const int tid = threadIdx.x;
    if (bid < NB_SPLIT) {
        int i = bid * 256 + tid;
        int row = i / (Hd / 4);
        int c4  = (i % (Hd / 4)) * 4;
        const float* src = (row < Bn * ENCn)
            ? enc + (size_t)row * Hd + c4
            : dec + (size_t)(row - Bn * ENCn) * Hd + c4;
        float4 v = *(const float4*)src;
        __nv_bfloat16 h0 = __float2bfloat16(v.x), h1 = __float2bfloat16(v.y);
        __nv_bfloat16 h2 = __float2bfloat16(v.z), h3 = __float2bfloat16(v.w);
        float l0 = v.x - __bfloat162float(h0), l1 = v.y - __bfloat162float(h1);
        float l2 = v.z - __bfloat162float(h2), l3 = v.w - __bfloat162float(h3);
        __nv_bfloat16* dh = dst + (size_t)row * K2 + c4;
        __nv_bfloat16* dl = dh + Hd;
        *(__nv_bfloat162*)(dh)     = __nv_bfloat162(h0, h1);
        *(__nv_bfloat162*)(dh + 2) = __nv_bfloat162(h2, h3);
        *(__nv_bfloat162*)(dl)     = __floats2bfloat162_rn(l0, l1);
        *(__nv_bfloat162*)(dl + 2) = __floats2bfloat162_rn(l2, l3);
    } else {
        __shared__ float t[32][33];
        const int b2  = bid - NB_SPLIT;
        const int z   = b2 / NB_WT;
        const int rem = b2 - z * NB_WT;
        const int bx  = rem % (Hd / 32);
        const int by  = rem / (Hd / 32);
        const float* W = z ? W2 : W1;
        __nv_bfloat16* d = z ? D2 : D1;
        const int k0 = by * 32, n0 = bx * 32;
        const int tx = tid & 31, ty = tid >> 5;
#pragma unroll
        for (int j = 0; j < 4; j++)
            t[ty + j * 8][tx] = W[(size_t)(k0 + ty + j * 8) * Hd + n0 + tx];
        __syncthreads();
#pragma unroll
        for (int j = 0; j < 4; j++) {
            int n = n0 + ty + j * 8;
            int k = k0 + tx;
            float x = t[tx][ty + j * 8];
            __nv_bfloat16 h = __float2bfloat16(x);
            float l = x - __bfloat162float(h);
            d[(size_t)n * K2 + k]      = h;
            d[(size_t)n * K2 + Hd + k] = __float2bfloat16(l);
        }
    }
}

// ---------------------------------------------------------------------------
// Tensor-core GEMM v3: 128x128 tile, 512 threads / 16 warps (warp tile 32x32,
// 4m x 4n) for 4 warps/SMSP latency hiding. Same 4-stage cp.async ring.
// Epilogue packs fp32 acc -> f16x2.
// ---------------------------------------------------------------------------
#define BK     32
#define ROWB   80
#define NCK    72
#define BUFB   (128 * ROWB)
#define STAGES 4
#define GEMM_SMEM (2 * STAGES * BUFB)   // 81920

__device__ __forceinline__ void chunk_off(int c, int& ao, int& bo) {
    const int phase = c / 24;
    const int r     = c - phase * 24;
    const int base  = r * (BK * 2);
    ao = base + (phase == 1 ? Hd * 2 : 0);
    bo = base + (phase == 2 ? Hd * 2 : 0);
}

__global__ __launch_bounds__(512, 1)
void gemm_tc_mma(const __nv_bfloat16* __restrict__ Asp,
                 const __nv_bfloat16* __restrict__ W1sp,
                 const __nv_bfloat16* __restrict__ W2sp,
                 uint32_t* __restrict__ Cenc, uint32_t* __restrict__ Cdec)
{
    extern __shared__ __align__(16) char gsm[];
    const uint32_t sA = smem_u32(gsm);
    const uint32_t sB = sA + STAGES * BUFB;

    const int tid    = threadIdx.x;
    const int wid    = tid >> 5;
    const int lane   = tid & 31;
    const int warp_m = wid & 3;          // 32-row band
    const int warp_n = wid >> 2;         // 32-col band (0..3)

    const int tileN = blockIdx.x * 128;
    const int mt    = blockIdx.y * 128;
    const __nv_bfloat16* Bsp;
    uint32_t* C; int crow;
    if (mt < Bn * ENCn) { Bsp = W1sp; C = Cenc; crow = mt; }
    else                { Bsp = W2sp; C = Cdec; crow = mt - Bn * ENCn; }

    const char* Agb = (const char*)(Asp + (size_t)mt   * K2);
    const char* Bgb = (const char*)(Bsp + (size_t)tileN * K2);

    // copy mapping: 512 segs per matrix per chunk; each thread: 1 A + 1 B seg
    const int rA = tid >> 2, qA = (tid & 3) * 16;

    float acc[2][4][4];
#pragma unroll
    for (int a = 0; a < 2; a++)
#pragma unroll
        for (int b = 0; b < 4; b++)
#pragma unroll
            for (int c = 0; c < 4; c++) acc[a][b][c] = 0.f;

#pragma unroll
    for (int c0 = 0; c0 < 3; c0++) {
        int ao, bo; chunk_off(c0, ao, bo);
        uint32_t da = sA + c0 * BUFB, db = sB + c0 * BUFB;
        CP_ASYNC16(da + rA * ROWB + qA, Agb + (size_t)rA * (K2 * 2) + ao + qA);
        CP_ASYNC16(db + rA * ROWB + qA, Bgb + (size_t)rA * (K2 * 2) + bo + qA);
        CP_COMMIT();
    }

    const uint32_t a_row  = warp_m * 32 + (lane & 15);
    const uint32_t a_colb = (lane >> 4) * 16;
    const uint32_t b_row  = warp_n * 32 + (lane & 7) + ((lane >> 4) & 1) * 8;
    const uint32_t b_colb = ((lane >> 3) & 1) * 16;

#pragma unroll 1
    for (int c = 0; c < NCK; c++) {
        const int buf = c & (STAGES - 1);
        CP_WAIT(2);
        __syncthreads();

        if (c + 3 < NCK) {
            int ao, bo; chunk_off(c + 3, ao, bo);
            const int nb = (c + 3) & (STAGES - 1);
            uint32_t da = sA + nb * BUFB, db = sB + nb * BUFB;
            CP_ASYNC16(da + rA * ROWB + qA, Agb + (size_t)rA * (K2 * 2) + ao + qA);
            CP_ASYNC16(db + rA * ROWB + qA, Bgb + (size_t)rA * (K2 * 2) + bo + qA);
        }
        CP_COMMIT();

        const uint32_t bA = sA + buf * BUFB;
        const uint32_t bB = sB + buf * BUFB;
#pragma unroll
        for (int ks = 0; ks < 2; ks++) {
            uint32_t afr[2][4], bfr[2][4];
#pragma unroll
            for (int m = 0; m < 2; m++)
                ldm_x4(bA + (a_row + m * 16) * ROWB + ks * 32 + a_colb, afr[m]);
#pragma unroll
            for (int n2 = 0; n2 < 2; n2++)
                ldm_x4(bB + (b_row + n2 * 16) * ROWB + ks * 32 + b_colb, bfr[n2]);
#pragma unroll
            for (int m = 0; m < 2; m++)
#pragma unroll
                for (int nt = 0; nt < 4; nt++)
                    mma16816(acc[m][nt], afr[m], &bfr[nt >> 1][(nt & 1) * 2]);
        }
    }

    // epilogue: pack adjacent column pairs -> f16x2
    const int rbase = crow + warp_m * 32 + (lane >> 2);
    const int cb2   = (tileN + warp_n * 32 + (lane & 3) * 2) >> 1;
#pragma unroll
    for (int m = 0; m < 2; m++) {
#pragma unroll
        for (int nt = 0; nt < 4; nt++) {
            uint32_t v0, v1;
            asm("cvt.rn.f16x2.f32 %0, %1, %2;" : "=r"(v0)
                : "f"(acc[m][nt][1]), "f"(acc[m][nt][0]));
            asm("cvt.rn.f16x2.f32 %0, %1, %2;" : "=r"(v1)
                : "f"(acc[m][nt][3]), "f"(acc[m][nt][2]));
            C[(size_t)(rbase + m * 16)     * (Hd / 2) + cb2 + nt * 4] = v0;
            C[(size_t)(rbase + m * 16 + 8) * (Hd / 2) + cb2 + nt * 4] = v1;
        }
    }
}

// ---------------------------------------------------------------------------
// Persistent score kernel (R13 f16 datapath — at MUFU element-rate floor)
// ---------------------------------------------------------------------------
#define SC_TILEB (8 * Hd * 2)            // bytes per enc tile (12288)
#define SC_SMEM  (2 * SC_TILEB)          // 24576

__global__ __launch_bounds__(512, 1) void score_kernel(
    const uint32_t* __restrict__ enc_h, const uint32_t* __restrict__ dec_h,
    const float* __restrict__ mask,  const float* __restrict__ vt,
    float* __restrict__ out)
{
    extern __shared__ char es[];
    const int tid  = threadIdx.x;
    const int wid  = tid >> 5;
    const int lane = tid & 31;
    const int G    = gridDim.x;
    const int ts   = (int)(((long long)blockIdx.x       * NTILES) / G);
    const int te   = (int)(((long long)(blockIdx.x + 1) * NTILES) / G);
    if (ts >= te) return;

    float4 vreg[6];
#pragma unroll
    for (int c = 0; c < 6; c++)
        vreg[c] = *(const float4*)(vt + c * 128 + lane * 4);

    uint2 a0p[6], a1p[6];
    int cur_strip = -1;
    const uint32_t es_s = smem_u32(es);

    {
        int b = ts >> 8, et = ts & 63;
        const char* src = (const char*)enc_h + ((size_t)b * ENCn + et * 8) * (Hd * 2);
        int seg = tid;
        CP_ASYNC16(es_s + seg * 16, src + seg * 16);
        seg = tid + 512;
        if (seg < 768) CP_ASYNC16(es_s + seg * 16, src + seg * 16);
        CP_COMMIT();
    }

#pragma unroll 1
    for (int t = ts; t < te; t++) {
        const int buf    = (t - ts) & 1;
        const int b      = t >> 8;
        const int dstrip = (t >> 6) & 3;
        const int et     = t & 63;
        const int strip  = t >> 6;

        CP_WAIT(0);
        __syncthreads();

        if (t + 1 < te) {
            int b2 = (t + 1) >> 8, et2 = (t + 1) & 63;
            const char* src = (const char*)enc_h + ((size_t)b2 * ENCn + et2 * 8) * (Hd * 2);
            uint32_t dst = es_s + (buf ^ 1) * SC_TILEB;
            int seg = tid;
            CP_ASYNC16(dst + seg * 16, src + seg * 16);
            seg = tid + 512;
            if (seg < 768) CP_ASYNC16(dst + seg * 16, src + seg * 16);
            CP_COMMIT();
        }

        const int drow0 = b * DECn + dstrip * 32 + 2 * wid;
        if (strip != cur_strip) {
            cur_strip = strip;
            const char* dp0 = (const char*)dec_h + (size_t)drow0 * (Hd * 2);
            const char* dp1 = dp0 + Hd * 2;
#pragma unroll
            for (int c = 0; c < 6; c++) {
                a0p[c] = *(const uint2*)(dp0 + c * 256 + lane * 8);
                a1p[c] = *(const uint2*)(dp1 + c * 256 + lane * 8);
            }
        }

        const char* eb = es + buf * SC_TILEB;
        const size_t half = (size_t)Bn * DECn * ENCn;

#pragma unroll 1
        for (int eo = 0; eo < 8; eo++) {
            const char* ep = eb + eo * (Hd * 2);
            float accA = 0.f, accB = 0.f;
#pragma unroll
            for (int c = 0; c < 6; c++) {
                uint2 bb = *(const uint2*)(ep + c * 256 + lane * 8);
                const float4 v = vreg[c];
                uint32_t x0, x1, y0, y1, t0, t1, t2, t3;
                asm("add.rn.f16x2 %0, %1, %2;" : "=r"(x0) : "r"(a0p[c].x), "r"(bb.x));
                asm("add.rn.f16x2 %0, %1, %2;" : "=r"(x1) : "r"(a0p[c].y), "r"(bb.y));
                asm("add.rn.f16x2 %0, %1, %2;" : "=r"(y0) : "r"(a1p[c].x), "r"(bb.x));
                asm("add.rn.f16x2 %0, %1, %2;" : "=r"(y1) : "r"(a1p[c].y), "r"(bb.y));
                asm("tanh.approx.f16x2 %0, %1;" : "=r"(t0) : "r"(x0));
                asm("tanh.approx.f16x2 %0, %1;" : "=r"(t1) : "r"(x1));
                asm("tanh.approx.f16x2 %0, %1;" : "=r"(t2) : "r"(y0));
                asm("tanh.approx.f16x2 %0, %1;" : "=r"(t3) : "r"(y1));
                float f00, f01, f02, f03, f10, f11, f12, f13;
                asm("{ .reg .b16 l, h; mov.b32 {l, h}, %2;\n\t"
                    "cvt.f32.f16 %0, l; cvt.f32.f16 %1, h; }"
                    : "=f"(f00), "=f"(f01) : "r"(t0));
                asm("{ .reg .b16 l, h; mov.b32 {l, h}, %2;\n\t"
                    "cvt.f32.f16 %0, l; cvt.f32.f16 %1, h; }"
                    : "=f"(f02), "=f"(f03) : "r"(t1));
                asm("{ .reg .b16 l, h; mov.b32 {l, h}, %2;\n\t"
                    "cvt.f32.f16 %0, l; cvt.f32.f16 %1, h; }"
                    : "=f"(f10), "=f"(f11) : "r"(t2));
                asm("{ .reg .b16 l, h; mov.b32 {l, h}, %2;\n\t"
                    "cvt.f32.f16 %0, l; cvt.f32.f16 %1, h; }"
                    : "=f"(f12), "=f"(f13) : "r"(t3));
                accA = fmaf(f00, v.x, accA);
                accA = fmaf(f01, v.y, accA);
                accA = fmaf(f02, v.z, accA);
                accA = fmaf(f03, v.w, accA);
                accB = fmaf(f10, v.x, accB);
                accB = fmaf(f11, v.y, accB);
                accB = fmaf(f12, v.z, accB);
                accB = fmaf(f13, v.w, accB);
            }
#pragma unroll
            for (int off = 16; off > 0; off >>= 1) {
                accA += __shfl_xor_sync(0xFFFFFFFFu, accA, off);
                accB += __shfl_xor_sync(0xFFFFFFFFu, accB, off);
            }
            if (lane == 0) {
                const int ecol = et * 8 + eo;
                const size_t i0 = (size_t)drow0 * ENCn + ecol;
                const size_t i1 = i0 + ENCn;
                out[i0]        = accA + mask[i0];
                out[half + i0] = accA;
                out[i1]        = accB + mask[i1];
                out[half + i1] = accB;
            }
        }
        __syncthreads();
    }
}

// ---------------------------------------------------------------------------
extern "C" void kernel_launch(void* const* d_in, const int* in_sizes, int n_in,
                              void* d_out, int out_size)
{
    const float* dec  = (const float*)d_in[0];
    const float* enc  = (const float*)d_in[1];
    const float* mask = (const float*)d_in[2];
    const float* W1   = (const float*)d_in[3];
    const float* W2   = (const float*)d_in[4];
    const float* vt   = (const float*)d_in[5];
    float* out = (float*)d_out;

    uint32_t *enc_h_p, *dec_h_p;
    __nv_bfloat16 *insp_p, *w1t_p, *w2t_p;
    cudaGetSymbolAddress((void**)&enc_h_p, g_enc_h);
    cudaGetSymbolAddress((void**)&dec_h_p, g_dec_h);
    cudaGetSymbolAddress((void**)&insp_p, g_in_split);
    cudaGetSymbolAddress((void**)&w1t_p, g_w1t);
    cudaGetSymbolAddress((void**)&w2t_p, g_w2t);

    int nsm = 148;
    cudaDeviceGetAttribute(&nsm, cudaDevAttrMultiProcessorCount, 0);

    prep_kernel<<<NB_SPLIT + 2 * NB_WT, 256>>>(enc, dec, W1, W2, insp_p, w1t_p, w2t_p);

    cudaFuncSetAttribute(gemm_tc_mma, cudaFuncAttributeMaxDynamicSharedMemorySize, GEMM_SMEM);
    gemm_tc_mma<<<dim3(Hd / 128, MROWS / 128), 512, GEMM_SMEM>>>(
        insp_p, w1t_p, w2t_p, enc_h_p, dec_h_p);

    cudaFuncSetAttribute(score_kernel, cudaFuncAttributeMaxDynamicSharedMemorySize, SC_SMEM);
    score_kernel<<<nsm, 512, SC_SMEM>>>(enc_h_p, dec_h_p, mask, vt, out);
}

// round 15
// speedup vs baseline: 1.0075x; 1.0075x over previous
#include <cuda_runtime.h>
#include <cuda_bf16.h>
#include <cstdint>

#define Hd   768
#define Bn   4
#define DECn 128
#define ENCn 512
#define K2   1536          // stored split K (hi | lo)
#define MROWS (Bn*ENCn + Bn*DECn)   // 2560
#define NTILES 2048        // 4 b * 8 dstrips(16) * 64 enc-tiles(8)

// ---------------- scratch (__device__ globals; no allocs allowed) ----------
__device__ float          g_enc_t[Bn * ENCn * Hd];
__device__ float          g_dec_t[Bn * DECn * Hd];
__device__ __nv_bfloat16  g_in_split[MROWS * K2];
__device__ __nv_bfloat16  g_w1t[Hd * K2];
__device__ __nv_bfloat16  g_w2t[Hd * K2];

__device__ __forceinline__ uint32_t smem_u32(const void* p) {
    return (uint32_t)__cvta_generic_to_shared(p);
}
__device__ __forceinline__ void ldm_x4(uint32_t addr, uint32_t* r) {
    asm volatile("ldmatrix.sync.aligned.m8n8.x4.shared.b16 {%0,%1,%2,%3}, [%4];"
        : "=r"(r[0]), "=r"(r[1]), "=r"(r[2]), "=r"(r[3]) : "r"(addr));
}
__device__ __forceinline__ void mma16816(float* d, const uint32_t* a, const uint32_t* b) {
    asm volatile("mma.sync.aligned.m16n8k16.row.col.f32.bf16.bf16.f32 "
        "{%0,%1,%2,%3}, {%4,%5,%6,%7}, {%8,%9}, {%0,%1,%2,%3};"
        : "+f"(d[0]), "+f"(d[1]), "+f"(d[2]), "+f"(d[3])
        : "r"(a[0]), "r"(a[1]), "r"(a[2]), "r"(a[3]), "r"(b[0]), "r"(b[1]));
}
#define CP_ASYNC16(saddr, gptr) \
    asm volatile("cp.async.cg.shared.global [%0], [%1], 16;" :: "r"(saddr), "l"(gptr))
#define CP_COMMIT() asm volatile("cp.async.commit_group;" ::: "memory")
#define CP_WAIT(n)  asm volatile("cp.async.wait_group %0;" :: "n"(n) : "memory")

// ---------------------------------------------------------------------------
// prep: split inputs hi|lo; transpose+split W1/W2   (unchanged, known-good)
// ---------------------------------------------------------------------------
#define NB_SPLIT (MROWS * (Hd / 4) / 256)          // 1920
#define NB_WT    ((Hd / 32) * (Hd / 32))           // 576 per matrix

__global__ __launch_bounds__(256) void prep_kernel(
    const float* __restrict__ enc, const float* __restrict__ dec,
    const float* __restrict__ W1,  const float* __restrict__ W2,
    __nv_bfloat16* __restrict__ dst,
    __nv_bfloat16* __restrict__ D1, __nv_bfloat16* __restrict__ D2)
{
    const int bid = blockIdx.x;
    const int tid = threadIdx.x;
    if (bid < NB_SPLIT) {
        int i = bid * 256 + tid;
        int row = i / (Hd / 4);
        int c4  = (i % (Hd / 4)) * 4;
        const float* src = (row < Bn * ENCn)
            ? enc + (size_t)row * Hd + c4
            : dec + (size_t)(row - Bn * ENCn) * Hd + c4;
        float4 v = *(const float4*)src;
        __nv_bfloat16 h0 = __float2bfloat16(v.x), h1 = __float2bfloat16(v.y);
        __nv_bfloat16 h2 = __float2bfloat16(v.z), h3 = __float2bfloat16(v.w);
        float l0 = v.x - __bfloat162float(h0), l1 = v.y - __bfloat162float(h1);
        float l2 = v.z - __bfloat162float(h2), l3 = v.w - __bfloat162float(h3);
        __nv_bfloat16* dh = dst + (size_t)row * K2 + c4;
        __nv_bfloat16* dl = dh + Hd;
        *(__nv_bfloat162*)(dh)     = __nv_bfloat162(h0, h1);
        *(__nv_bfloat162*)(dh + 2) = __nv_bfloat162(h2, h3);
        *(__nv_bfloat162*)(dl)     = __floats2bfloat162_rn(l0, l1);
        *(__nv_bfloat162*)(dl + 2) = __floats2bfloat162_rn(l2, l3);
    } else {
        __shared__ float t[32][33];
        const int b2  = bid - NB_SPLIT;
        const int z   = b2 / NB_WT;
        const int rem = b2 - z * NB_WT;
        const int bx  = rem % (Hd / 32);
        const int by  = rem / (Hd / 32);
        const float* W = z ? W2 : W1;
        __nv_bfloat16* d = z ? D2 : D1;
        const int k0 = by * 32, n0 = bx * 32;
        const int tx = tid & 31, ty = tid >> 5;
#pragma unroll
        for (int j = 0; j < 4; j++)
            t[ty + j * 8][tx] = W[(size_t)(k0 + ty + j * 8) * Hd + n0 + tx];
        __syncthreads();
#pragma unroll
        for (int j = 0; j < 4; j++) {
            int n = n0 + ty + j * 8;
            int k = k0 + tx;
            float x = t[tx][ty + j * 8];
            __nv_bfloat16 h = __float2bfloat16(x);
            float l = x - __bfloat162float(h);
            d[(size_t)n * K2 + k]      = h;
            d[(size_t)n * K2 + Hd + k] = __float2bfloat16(l);
        }
    }
}

// ---------------------------------------------------------------------------
// Tensor-core GEMM (R6 4-stage, 256 threads — best-known config)
// ---------------------------------------------------------------------------
#define BK     32
#define ROWB   80
#define NCK    72
#define BUFB   (128 * ROWB)
#define STAGES 4
#define GEMM_SMEM (2 * STAGES * BUFB)   // 81920

__device__ __forceinline__ void chunk_off(int c, int& ao, int& bo) {
    const int phase = c / 24;
    const int r     = c - phase * 24;
    const int base  = r * (BK * 2);
    ao = base + (phase == 1 ? Hd * 2 : 0);
    bo = base + (phase == 2 ? Hd * 2 : 0);
}

__global__ __launch_bounds__(256, 1)
void gemm_tc_mma(const __nv_bfloat16* __restrict__ Asp,
                 const __nv_bfloat16* __restrict__ W1sp,
                 const __nv_bfloat16* __restrict__ W2sp,
                 float* __restrict__ Cenc, float* __restrict__ Cdec)
{
    extern __shared__ __align__(16) char gsm[];
    const uint32_t sA = smem_u32(gsm);
    const uint32_t sB = sA + STAGES * BUFB;

    const int tid    = threadIdx.x;
    const int wid    = tid >> 5;
    const int lane   = tid & 31;
    const int warp_m = wid & 3;
    const int warp_n = wid >> 2;

    const int tileN = blockIdx.x * 128;
    const int mt    = blockIdx.y * 128;
    const __nv_bfloat16* Bsp;
    float* C; int crow;
    if (mt < Bn * ENCn) { Bsp = W1sp; C = Cenc; crow = mt; }
    else                { Bsp = W2sp; C = Cdec; crow = mt - Bn * ENCn; }

    const char* Agb = (const char*)(Asp + (size_t)mt   * K2);
    const char* Bgb = (const char*)(Bsp + (size_t)tileN * K2);

    const int rA0 = tid >> 2,         qA0 = (tid & 3) * 16;
    const int rA1 = (tid + 256) >> 2, qA1 = (tid & 3) * 16;

    float acc[2][8][4];
#pragma unroll
    for (int a = 0; a < 2; a++)
#pragma unroll
        for (int b = 0; b < 8; b++)
#pragma unroll
            for (int c = 0; c < 4; c++) acc[a][b][c] = 0.f;

#pragma unroll
    for (int c0 = 0; c0 < 3; c0++) {
        int ao, bo; chunk_off(c0, ao, bo);
        uint32_t da = sA + c0 * BUFB, db = sB + c0 * BUFB;
        CP_ASYNC16(da + rA0 * ROWB + qA0, Agb + (size_t)rA0 * (K2 * 2) + ao + qA0);
        CP_ASYNC16(da + rA1 * ROWB + qA1, Agb + (size_t)rA1 * (K2 * 2) + ao + qA1);
        CP_ASYNC16(db + rA0 * ROWB + qA0, Bgb + (size_t)rA0 * (K2 * 2) + bo + qA0);
        CP_ASYNC16(db + rA1 * ROWB + qA1, Bgb + (size_t)rA1 * (K2 * 2) + bo + qA1);
        CP_COMMIT();
    }

    const uint32_t a_row  = warp_m * 32 + (lane & 15);
    const uint32_t a_colb = (lane >> 4) * 16;
    const uint32_t b_row  = warp_n * 64 + (lane & 7) + ((lane >> 4) & 1) * 8;
    const uint32_t b_colb = ((lane >> 3) & 1) * 16;

#pragma unroll 1
    for (int c = 0; c < NCK; c++) {
        const int buf = c & (STAGES - 1);
        CP_WAIT(2);
        __syncthreads();

        if (c + 3 < NCK) {
            int ao, bo; chunk_off(c + 3, ao, bo);
            const int nb = (c + 3) & (STAGES - 1);
            uint32_t da = sA + nb * BUFB, db = sB + nb * BUFB;
            CP_ASYNC16(da + rA0 * ROWB + qA0, Agb + (size_t)rA0 * (K2 * 2) + ao + qA0);
            CP_ASYNC16(da + rA1 * ROWB + qA1, Agb + (size_t)rA1 * (K2 * 2) + ao + qA1);
            CP_ASYNC16(db + rA0 * ROWB + qA0, Bgb + (size_t)rA0 * (K2 * 2) + bo + qA0);
            CP_ASYNC16(db + rA1 * ROWB + qA1, Bgb + (size_t)rA1 * (K2 * 2) + bo + qA1);
        }
        CP_COMMIT();

        const uint32_t bA = sA + buf * BUFB;
        const uint32_t bB = sB + buf * BUFB;
#pragma unroll
        for (int ks = 0; ks < 2; ks++) {
            uint32_t afr[2][4], bfr[4][4];
#pragma unroll
            for (int m = 0; m < 2; m++)
                ldm_x4(bA + (a_row + m * 16) * ROWB + ks * 32 + a_colb, afr[m]);
#pragma unroll
            for (int n2 = 0; n2 < 4; n2++)
                ldm_x4(bB + (b_row + n2 * 16) * ROWB + ks * 32 + b_colb, bfr[n2]);
#pragma unroll
            for (int m = 0; m < 2; m++)
#pragma unroll
                for (int nt = 0; nt < 8; nt++)
                    mma16816(acc[m][nt], afr[m], &bfr[nt >> 1][(nt & 1) * 2]);
        }
    }

    const int rbase = crow + warp_m * 32 + (lane >> 2);
    const int cbase = tileN + warp_n * 64 + (lane & 3) * 2;
#pragma unroll
    for (int m = 0; m < 2; m++) {
#pragma unroll
        for (int nt = 0; nt < 8; nt++) {
            float* p0 = C + (size_t)(rbase + m * 16)     * Hd + cbase + nt * 8;
            float* p1 = C + (size_t)(rbase + m * 16 + 8) * Hd + cbase + nt * 8;
            *(float2*)p0 = make_float2(acc[m][nt][0], acc[m][nt][1]);
            *(float2*)p1 = make_float2(acc[m][nt][2], acc[m][nt][3]);
        }
    }
}

// ---------------------------------------------------------------------------
// Persistent score kernel v6: R9 datapath, but TWO 256-thread blocks per SM
// (8 warps each) so block barriers / shfl-reduces of one block overlap with
// the other block's compute. Tile = 16 dec x 8 enc; warp w owns dec rows
// 2w, 2w+1 (registers). e-outer/c-inner, f16x2 tanh, fp32 accum.
// ---------------------------------------------------------------------------
#define SC_TILEF (8 * Hd)            // floats per enc tile (6144)
#define SC_SMEM  (2 * SC_TILEF * 4)  // 49152 bytes

__global__ __launch_bounds__(256, 2) void score_kernel(
    const float* __restrict__ enc_t, const float* __restrict__ dec_t,
    const float* __restrict__ mask,  const float* __restrict__ vt,
    float* __restrict__ out)
{
    extern __shared__ float es[];
    const int tid  = threadIdx.x;
    const int wid  = tid >> 5;            // 0..7
    const int lane = tid & 31;
    const int G    = gridDim.x;
    const int ts   = (int)(((long long)blockIdx.x       * NTILES) / G);
    const int te   = (int)(((long long)(blockIdx.x + 1) * NTILES) / G);
    if (ts >= te) return;

    float4 vreg[6];
#pragma unroll
    for (int c = 0; c < 6; c++)
        vreg[c] = *(const float4*)(vt + c * 128 + lane * 4);

    float4 a0r[6], a1r[6];
    int cur_strip = -1;
    const uint32_t es_s = smem_u32(es);

    // tile mapping: b = t>>9, dstrip(16 rows) = (t>>6)&7, et = t&63
    {
        int b = ts >> 9, et = ts & 63;
        const float* src = enc_t + ((size_t)b * ENCn + et * 8) * Hd;
#pragma unroll
        for (int i = 0; i < 6; i++) {
            int seg = i * 256 + tid;          // 0..1535
            CP_ASYNC16(es_s + seg * 16, src + seg * 4);
        }
        CP_COMMIT();
    }

#pragma unroll 1
    for (int t = ts; t < te; t++) {
        const int buf    = (t - ts) & 1;
        const int b      = t >> 9;
        const int dstrip = (t >> 6) & 7;
        const int et     = t & 63;
        const int strip  = t >> 6;            // (b,dstrip) id

        CP_WAIT(0);
        __syncthreads();

        if (t + 1 < te) {
            int b2 = (t + 1) >> 9, et2 = (t + 1) & 63;
            const float* src = enc_t + ((size_t)b2 * ENCn + et2 * 8) * Hd;
            uint32_t dst = es_s + (buf ^ 1) * (SC_TILEF * 4);
#pragma unroll
            for (int i = 0; i < 6; i++) {
                int seg = i * 256 + tid;
                CP_ASYNC16(dst + seg * 16, src + seg * 4);
            }
            CP_COMMIT();
        }

        const int drow0 = b * DECn + dstrip * 16 + 2 * wid;
        if (strip != cur_strip) {
            cur_strip = strip;
            const float* dp0 = dec_t + (size_t)drow0 * Hd;
            const float* dp1 = dp0 + Hd;
#pragma unroll
            for (int c = 0; c < 6; c++) {
                a0r[c] = *(const float4*)(dp0 + c * 128 + lane * 4);
                a1r[c] = *(const float4*)(dp1 + c * 128 + lane * 4);
            }
        }

        const float* eb = es + buf * SC_TILEF;
        const size_t half = (size_t)Bn * DECn * ENCn;

#pragma unroll 1
        for (int eo = 0; eo < 8; eo++) {
            const float* ep = eb + eo * Hd;
            float accA = 0.f, accB = 0.f;
#pragma unroll
            for (int c = 0; c < 6; c++) {
                float4 bb = *(const float4*)(ep + c * 128 + lane * 4);
                const float4 a0 = a0r[c];
                const float4 a1 = a1r[c];
                const float4 v  = vreg[c];
                float x00 = a0.x + bb.x, x01 = a0.y + bb.y;
                float x02 = a0.z + bb.z, x03 = a0.w + bb.w;
                float x10 = a1.x + bb.x, x11 = a1.y + bb.y;
                float x12 = a1.z + bb.z, x13 = a1.w + bb.w;
                uint32_t p0, p1, p2, p3, t0, t1, t2, t3;
                asm("cvt.rn.f16x2.f32 %0, %1, %2;" : "=r"(p0) : "f"(x01), "f"(x00));
                asm("cvt.rn.f16x2.f32 %0, %1, %2;" : "=r"(p1) : "f"(x03), "f"(x02));
                asm("cvt.rn.f16x2.f32 %0, %1, %2;" : "=r"(p2) : "f"(x11), "f"(x10));
                asm("cvt.rn.f16x2.f32 %0, %1, %2;" : "=r"(p3) : "f"(x13), "f"(x12));
                asm("tanh.approx.f16x2 %0, %1;" : "=r"(t0) : "r"(p0));
                asm("tanh.approx.f16x2 %0, %1;" : "=r"(t1) : "r"(p1));
                asm("tanh.approx.f16x2 %0, %1;" : "=r"(t2) : "r"(p2));
                asm("tanh.approx.f16x2 %0, %1;" : "=r"(t3) : "r"(p3));
                float f00, f01, f02, f03, f10, f11, f12, f13;
                asm("{ .reg .b16 l, h; mov.b32 {l, h}, %2;\n\t"
                    "cvt.f32.f16 %0, l; cvt.f32.f16 %1, h; }"
                    : "=f"(f00), "=f"(f01) : "r"(t0));
                asm("{ .reg .b16 l, h; mov.b32 {l, h}, %2;\n\t"
                    "cvt.f32.f16 %0, l; cvt.f32.f16 %1, h; }"
                    : "=f"(f02), "=f"(f03) : "r"(t1));
                asm("{ .reg .b16 l, h; mov.b32 {l, h}, %2;\n\t"
                    "cvt.f32.f16 %0, l; cvt.f32.f16 %1, h; }"
                    : "=f"(f10), "=f"(f11) : "r"(t2));
                asm("{ .reg .b16 l, h; mov.b32 {l, h}, %2;\n\t"
                    "cvt.f32.f16 %0, l; cvt.f32.f16 %1, h; }"
                    : "=f"(f12), "=f"(f13) : "r"(t3));
                accA = fmaf(f00, v.x, accA);
                accA = fmaf(f01, v.y, accA);
                accA = fmaf(f02, v.z, accA);
                accA = fmaf(f03, v.w, accA);
                accB = fmaf(f10, v.x, accB);
                accB = fmaf(f11, v.y, accB);
                accB = fmaf(f12, v.z, accB);
                accB = fmaf(f13, v.w, accB);
            }
#pragma unroll
            for (int off = 16; off > 0; off >>= 1) {
                accA += __shfl_xor_sync(0xFFFFFFFFu, accA, off);
                accB += __shfl_xor_sync(0xFFFFFFFFu, accB, off);
            }
            if (lane == 0) {
                const int ecol = et * 8 + eo;
                const size_t i0 = (size_t)drow0 * ENCn + ecol;
                const size_t i1 = i0 + ENCn;
                out[i0]        = accA + mask[i0];
                out[half + i0] = accA;
                out[i1]        = accB + mask[i1];
                out[half + i1] = accB;
            }
        }
        __syncthreads();
    }
}

// ---------------------------------------------------------------------------
extern "C" void kernel_launch(void* const* d_in, const int* in_sizes, int n_in,
                              void* d_out, int out_size)
{
    const float* dec  = (const float*)d_in[0];
    const float* enc  = (const float*)d_in[1];
    const float* mask = (const float*)d_in[2];
    const float* W1   = (const float*)d_in[3];
    const float* W2   = (const float*)d_in[4];
    const float* vt   = (const float*)d_in[5];
    float* out = (float*)d_out;

    float *enc_t_p, *dec_t_p;
    __nv_bfloat16 *insp_p, *w1t_p, *w2t_p;
    cudaGetSymbolAddress((void**)&enc_t_p, g_enc_t);
    cudaGetSymbolAddress((void**)&dec_t_p, g_dec_t);
    cudaGetSymbolAddress((void**)&insp_p, g_in_split);
    cudaGetSymbolAddress((void**)&w1t_p, g_w1t);
    cudaGetSymbolAddress((void**)&w2t_p, g_w2t);

    int nsm = 148;
    cudaDeviceGetAttribute(&nsm, cudaDevAttrMultiProcessorCount, 0);

    prep_kernel<<<NB_SPLIT + 2 * NB_WT, 256>>>(enc, dec, W1, W2, insp_p, w1t_p, w2t_p);

    cudaFuncSetAttribute(gemm_tc_mma, cudaFuncAttributeMaxDynamicSharedMemorySize, GEMM_SMEM);
    gemm_tc_mma<<<dim3(Hd / 128, MROWS / 128), 256, GEMM_SMEM>>>(
        insp_p, w1t_p, w2t_p, enc_t_p, dec_t_p);

    cudaFuncSetAttribute(score_kernel, cudaFuncAttributeMaxDynamicSharedMemorySize, SC_SMEM);
    score_kernel<<<2 * nsm, 256, SC_SMEM>>>(enc_t_p, dec_t_p, mask, vt, out);
}

// round 16
// speedup vs baseline: 1.0946x; 1.0865x over previous
#include <cuda_runtime.h>
#include <cuda_bf16.h>
#include <cstdint>

#define Hd   768
#define Bn   4
#define DECn 128
#define ENCn 512
#define K2   1536          // stored split K (hi | lo)
#define MROWS (Bn*ENCn + Bn*DECn)   // 2560
#define NTILES 1024        // 4 b * 4 dstrips(32) * 64 enc-tiles(8)

// ---------------- scratch (__device__ globals; no allocs allowed) ----------
__device__ float          g_enc_t[Bn * ENCn * Hd];
__device__ float          g_dec_t[Bn * DECn * Hd];
__device__ __nv_bfloat16  g_in_split[MROWS * K2];
__device__ __nv_bfloat16  g_w1t[Hd * K2];
__device__ __nv_bfloat16  g_w2t[Hd * K2];

__device__ __forceinline__ uint32_t smem_u32(const void* p) {
    return (uint32_t)__cvta_generic_to_shared(p);
}
__device__ __forceinline__ void ldm_x4(uint32_t addr, uint32_t* r) {
    asm volatile("ldmatrix.sync.aligned.m8n8.x4.shared.b16 {%0,%1,%2,%3}, [%4];"
        : "=r"(r[0]), "=r"(r[1]), "=r"(r[2]), "=r"(r[3]) : "r"(addr));
}
__device__ __forceinline__ void mma16816(float* d, const uint32_t* a, const uint32_t* b) {
    asm volatile("mma.sync.aligned.m16n8k16.row.col.f32.bf16.bf16.f32 "
        "{%0,%1,%2,%3}, {%4,%5,%6,%7}, {%8,%9}, {%0,%1,%2,%3};"
        : "+f"(d[0]), "+f"(d[1]), "+f"(d[2]), "+f"(d[3])
        : "r"(a[0]), "r"(a[1]), "r"(a[2]), "r"(a[3]), "r"(b[0]), "r"(b[1]));
}
#define CP_ASYNC16(saddr, gptr) \
    asm volatile("cp.async.cg.shared.global [%0], [%1], 16;" :: "r"(saddr), "l"(gptr))
#define CP_COMMIT() asm volatile("cp.async.commit_group;" ::: "memory")
#define CP_WAIT(n)  asm volatile("cp.async.wait_group %0;" :: "n"(n) : "memory")

// ---------------------------------------------------------------------------
// prep: split inputs hi|lo; transpose+split W1/W2   (unchanged, known-good)
// ---------------------------------------------------------------------------
#define NB_SPLIT (MROWS * (Hd / 4) / 256)          // 1920
#define NB_WT    ((Hd / 32) * (Hd / 32))           // 576 per matrix

__global__ __launch_bounds__(256) void prep_kernel(
    const float* __restrict__ enc, const float* __restrict__ dec,
    const float* __restrict__ W1,  const float* __restrict__ W2,
    __nv_bfloat16* __restrict__ dst,
    __nv_bfloat16* __restrict__ D1, __nv_bfloat16* __restrict__ D2)
{
    const int bid = blockIdx.x;
    const int tid = threadIdx.x;
    if (bid < NB_SPLIT) {
        int i = bid * 256 + tid;
        int row = i / (Hd / 4);
        int c4  = (i % (Hd / 4)) * 4;
        const float* src = (row < Bn * ENCn)
            ? enc + (size_t)row * Hd + c4
            : dec + (size_t)(row - Bn * ENCn) * Hd + c4;
        float4 v = *(const float4*)src;
        __nv_bfloat16 h0 = __float2bfloat16(v.x), h1 = __float2bfloat16(v.y);
        __nv_bfloat16 h2 = __float2bfloat16(v.z), h3 = __float2bfloat16(v.w);
        float l0 = v.x - __bfloat162float(h0), l1 = v.y - __bfloat162float(h1);
        float l2 = v.z - __bfloat162float(h2), l3 = v.w - __bfloat162float(h3);
        __nv_bfloat16* dh = dst + (size_t)row * K2 + c4;
        __nv_bfloat16* dl = dh + Hd;
        *(__nv_bfloat162*)(dh)     = __nv_bfloat162(h0, h1);
        *(__nv_bfloat162*)(dh + 2) = __nv_bfloat162(h2, h3);
        *(__nv_bfloat162*)(dl)     = __floats2bfloat162_rn(l0, l1);
        *(__nv_bfloat162*)(dl + 2) = __floats2bfloat162_rn(l2, l3);
    } else {
        __shared__ float t[32][33];
        const int b2  = bid - NB_SPLIT;
        const int z   = b2 / NB_WT;
        const int rem = b2 - z * NB_WT;
        const int bx  = rem % (Hd / 32);
        const int by  = rem / (Hd / 32);
        const float* W = z ? W2 : W1;
        __nv_bfloat16* d = z ? D2 : D1;
        const int k0 = by * 32, n0 = bx * 32;
        const int tx = tid & 31, ty = tid >> 5;
#pragma unroll
        for (int j = 0; j < 4; j++)
            t[ty + j * 8][tx] = W[(size_t)(k0 + ty + j * 8) * Hd + n0 + tx];
        __syncthreads();
#pragma unroll
        for (int j = 0; j < 4; j++) {
            int n = n0 + ty + j * 8;
            int k = k0 + tx;
            float x = t[tx][ty + j * 8];
            __nv_bfloat16 h = __float2bfloat16(x);
            float l = x - __bfloat162float(h);
            d[(size_t)n * K2 + k]      = h;
            d[(size_t)n * K2 + Hd + k] = __float2bfloat16(l);
        }
    }
}

// ---------------------------------------------------------------------------
// Tensor-core GEMM v4: phase-fused stages. Stage r = k-range r with all four
// operand buffers {A-hi, A-lo, B-hi, B-lo}. 24 stages (vs 72 chunks): one
// CP_WAIT + one __syncthreads per stage; fragments reused across the three
// precision products (ah*bh, al*bh, ah*bl). 3-stage ring, 120KB smem.
// ---------------------------------------------------------------------------
#define BK      32
#define ROWB    80
#define NRANGE  24
#define BUFB    (128 * ROWB)             // 10240
#define STAGEB  (4 * BUFB)               // 40960: [Ah|Al|Bh|Bl]
#define RSTAGES 3
#define GEMM_SMEM (RSTAGES * STAGEB)     // 122880

__global__ __launch_bounds__(256, 1)
void gemm_tc_mma(const __nv_bfloat16* __restrict__ Asp,
                 const __nv_bfloat16* __restrict__ W1sp,
                 const __nv_bfloat16* __restrict__ W2sp,
                 float* __restrict__ Cenc, float* __restrict__ Cdec)
{
    extern __shared__ __align__(16) char gsm[];
    const uint32_t sbase = smem_u32(gsm);

    const int tid    = threadIdx.x;
    const int wid    = tid >> 5;
    const int lane   = tid & 31;
    const int warp_m = wid & 3;
    const int warp_n = wid >> 2;

    const int tileN = blockIdx.x * 128;
    const int mt    = blockIdx.y * 128;
    const __nv_bfloat16* Bsp;
    float* C; int crow;
    if (mt < Bn * ENCn) { Bsp = W1sp; C = Cenc; crow = mt; }
    else                { Bsp = W2sp; C = Cdec; crow = mt - Bn * ENCn; }

    const char* Agb = (const char*)(Asp + (size_t)mt   * K2);
    const char* Bgb = (const char*)(Bsp + (size_t)tileN * K2);

    // per-thread copy mapping: each 128x32 buffer = 512 segs; 2 segs/thread
    const int rA0 = tid >> 2,         qA0 = (tid & 3) * 16;
    const int rA1 = (tid + 256) >> 2, qA1 = (tid & 3) * 16;

    float acc[2][8][4];
#pragma unroll
    for (int a = 0; a < 2; a++)
#pragma unroll
        for (int b = 0; b < 8; b++)
#pragma unroll
            for (int c = 0; c < 4; c++) acc[a][b][c] = 0.f;

    // issue all 4 buffers of k-range r into ring slot r%RSTAGES
    auto issue = [&](int r) {
        const uint32_t st = sbase + (r % RSTAGES) * STAGEB;
        const int oh = r * (BK * 2);            // hi byte offset
        const int ol = Hd * 2 + r * (BK * 2);   // lo byte offset
        const uint32_t sAh = st,             sAl = st + BUFB;
        const uint32_t sBh = st + 2 * BUFB,  sBl = st + 3 * BUFB;
        CP_ASYNC16(sAh + rA0 * ROWB + qA0, Agb + (size_t)rA0 * (K2 * 2) + oh + qA0);
        CP_ASYNC16(sAh + rA1 * ROWB + qA1, Agb + (size_t)rA1 * (K2 * 2) + oh + qA1);
        CP_ASYNC16(sAl + rA0 * ROWB + qA0, Agb + (size_t)rA0 * (K2 * 2) + ol + qA0);
        CP_ASYNC16(sAl + rA1 * ROWB + qA1, Agb + (size_t)rA1 * (K2 * 2) + ol + qA1);
        CP_ASYNC16(sBh + rA0 * ROWB + qA0, Bgb + (size_t)rA0 * (K2 * 2) + oh + qA0);
        CP_ASYNC16(sBh + rA1 * ROWB + qA1, Bgb + (size_t)rA1 * (K2 * 2) + oh + qA1);
        CP_ASYNC16(sBl + rA0 * ROWB + qA0, Bgb + (size_t)rA0 * (K2 * 2) + ol + qA0);
        CP_ASYNC16(sBl + rA1 * ROWB + qA1, Bgb + (size_t)rA1 * (K2 * 2) + ol + qA1);
    };

    // prologue: stages 0,1 (one group each)
    issue(0); CP_COMMIT();
    issue(1); CP_COMMIT();

    const uint32_t a_row  = warp_m * 32 + (lane & 15);
    const uint32_t a_colb = (lane >> 4) * 16;
    const uint32_t b_row  = warp_n * 64 + (lane & 7) + ((lane >> 4) & 1) * 8;
    const uint32_t b_colb = ((lane >> 3) & 1) * 16;

#pragma unroll 1
    for (int r = 0; r < NRANGE; r++) {
        CP_WAIT(1);              // stage r resident (r+1 may pend)
        __syncthreads();         // + guards ring slot reuse (r-1 computed)

        if (r + 2 < NRANGE) issue(r + 2);
        CP_COMMIT();             // empty group past end keeps accounting

        const uint32_t st = sbase + (r % RSTAGES) * STAGEB;
        const uint32_t sAh = st,            sAl = st + BUFB;
        const uint32_t sBh = st + 2 * BUFB, sBl = st + 3 * BUFB;

#pragma unroll
        for (int ks = 0; ks < 2; ks++) {
            const uint32_t ko = ks * 32;
            uint32_t ah[2][4], al[2][4], bh[4][4], bl[4][4];
            // hi fragments
#pragma unroll
            for (int n2 = 0; n2 < 4; n2++)
                ldm_x4(sBh + (b_row + n2 * 16) * ROWB + ko + b_colb, bh[n2]);
#pragma unroll
            for (int m = 0; m < 2; m++)
                ldm_x4(sAh + (a_row + m * 16) * ROWB + ko + a_colb, ah[m]);
            // ah * bh
#pragma unroll
            for (int m = 0; m < 2; m++)
#pragma unroll
                for (int nt = 0; nt < 8; nt++)
                    mma16816(acc[m][nt], ah[m], &bh[nt >> 1][(nt & 1) * 2]);
            // al * bh
#pragma unroll
            for (int m = 0; m < 2; m++)
                ldm_x4(sAl + (a_row + m * 16) * ROWB + ko + a_colb, al[m]);
#pragma unroll
            for (int m = 0; m < 2; m++)
#pragma unroll
                for (int nt = 0; nt < 8; nt++)
                    mma16816(acc[m][nt], al[m], &bh[nt >> 1][(nt & 1) * 2]);
            // ah * bl
#pragma unroll
            for (int n2 = 0; n2 < 4; n2++)
                ldm_x4(sBl + (b_row + n2 * 16) * ROWB + ko + b_colb, bl[n2]);
#pragma unroll
            for (int m = 0; m < 2; m++)
#pragma unroll
                for (int nt = 0; nt < 8; nt++)
                    mma16816(acc[m][nt], ah[m], &bl[nt >> 1][(nt & 1) * 2]);
        }
    }

    const int rbase = crow + warp_m * 32 + (lane >> 2);
    const int cbase = tileN + warp_n * 64 + (lane & 3) * 2;
#pragma unroll
    for (int m = 0; m < 2; m++) {
#pragma unroll
        for (int nt = 0; nt < 8; nt++) {
            float* p0 = C + (size_t)(rbase + m * 16)     * Hd + cbase + nt * 8;
            float* p1 = C + (size_t)(rbase + m * 16 + 8) * Hd + cbase + nt * 8;
            *(float2*)p0 = make_float2(acc[m][nt][0], acc[m][nt][1]);
            *(float2*)p1 = make_float2(acc[m][nt][2], acc[m][nt][3]);
        }
    }
}

// ---------------------------------------------------------------------------
// Persistent score kernel (R9 exact — best known: tile 32 dec x 8 enc,
// 16 warps, dec pair in regs, e-outer/c-inner, f16x2 tanh)
// ---------------------------------------------------------------------------
#define SC_TILEF (8 * Hd)            // floats per enc tile (6144)
#define SC_SMEM  (2 * SC_TILEF * 4)  // 49152 bytes

__global__ __launch_bounds__(512, 1) void score_kernel(
    const float* __restrict__ enc_t, const float* __restrict__ dec_t,
    const float* __restrict__ mask,  const float* __restrict__ vt,
    float* __restrict__ out)
{
    extern __shared__ float es[];
    const int tid  = threadIdx.x;
    const int wid  = tid >> 5;
    const int lane = tid & 31;
    const int G    = gridDim.x;
    const int ts   = (int)(((long long)blockIdx.x       * NTILES) / G);
    const int te   = (int)(((long long)(blockIdx.x + 1) * NTILES) / G);
    if (ts >= te) return;

    float4 vreg[6];
#pragma unroll
    for (int c = 0; c < 6; c++)
        vreg[c] = *(const float4*)(vt + c * 128 + lane * 4);

    float4 a0r[6], a1r[6];
    int cur_strip = -1;
    const uint32_t es_s = smem_u32(es);

    {
        int b = ts >> 8, et = ts & 63;
        const float* src = enc_t + ((size_t)b * ENCn + et * 8) * Hd;
#pragma unroll
        for (int i = 0; i < 3; i++) {
            int seg = i * 512 + tid;
            CP_ASYNC16(es_s + seg * 16, src + seg * 4);
        }
        CP_COMMIT();
    }

#pragma unroll 1
    for (int t = ts; t < te; t++) {
        const int buf    = (t - ts) & 1;
        const int b      = t >> 8;
        const int dstrip = (t >> 6) & 3;
        const int et     = t & 63;
        const int strip  = t >> 6;

        CP_WAIT(0);
        __syncthreads();

        if (t + 1 < te) {
            int b2 = (t + 1) >> 8, et2 = (t + 1) & 63;
            const float* src = enc_t + ((size_t)b2 * ENCn + et2 * 8) * Hd;
            uint32_t dst = es_s + (buf ^ 1) * (SC_TILEF * 4);
#pragma unroll
            for (int i = 0; i < 3; i++) {
                int seg = i * 512 + tid;
                CP_ASYNC16(dst + seg * 16, src + seg * 4);
            }
            CP_COMMIT();
        }

        const int drow0 = b * DECn + dstrip * 32 + 2 * wid;
        if (strip != cur_strip) {
            cur_strip = strip;
            const float* dp0 = dec_t + (size_t)drow0 * Hd;
            const float* dp1 = dp0 + Hd;
#pragma unroll
            for (int c = 0; c < 6; c++) {
                a0r[c] = *(const float4*)(dp0 + c * 128 + lane * 4);
                a1r[c] = *(const float4*)(dp1 + c * 128 + lane * 4);
            }
        }

        const float* eb = es + buf * SC_TILEF;
        const size_t half = (size_t)Bn * DECn * ENCn;

#pragma unroll 1
        for (int eo = 0; eo < 8; eo++) {
            const float* ep = eb + eo * Hd;
            float accA = 0.f, accB = 0.f;
#pragma unroll
            for (int c = 0; c < 6; c++) {
                float4 bb = *(const float4*)(ep + c * 128 + lane * 4);
                const float4 a0 = a0r[c];
                const float4 a1 = a1r[c];
                const float4 v  = vreg[c];
                float x00 = a0.x + bb.x, x01 = a0.y + bb.y;
                float x02 = a0.z + bb.z, x03 = a0.w + bb.w;
                float x10 = a1.x + bb.x, x11 = a1.y + bb.y;
                float x12 = a1.z + bb.z, x13 = a1.w + bb.w;
                uint32_t p0, p1, p2, p3, t0, t1, t2, t3;
                asm("cvt.rn.f16x2.f32 %0, %1, %2;" : "=r"(p0) : "f"(x01), "f"(x00));
                asm("cvt.rn.f16x2.f32 %0, %1, %2;" : "=r"(p1) : "f"(x03), "f"(x02));
                asm("cvt.rn.f16x2.f32 %0, %1, %2;" : "=r"(p2) : "f"(x11), "f"(x10));
                asm("cvt.rn.f16x2.f32 %0, %1, %2;" : "=r"(p3) : "f"(x13), "f"(x12));
                asm("tanh.approx.f16x2 %0, %1;" : "=r"(t0) : "r"(p0));
                asm("tanh.approx.f16x2 %0, %1;" : "=r"(t1) : "r"(p1));
                asm("tanh.approx.f16x2 %0, %1;" : "=r"(t2) : "r"(p2));
                asm("tanh.approx.f16x2 %0, %1;" : "=r"(t3) : "r"(p3));
                float f00, f01, f02, f03, f10, f11, f12, f13;
                asm("{ .reg .b16 l, h; mov.b32 {l, h}, %2;\n\t"
                    "cvt.f32.f16 %0, l; cvt.f32.f16 %1, h; }"
                    : "=f"(f00), "=f"(f01) : "r"(t0));
                asm("{ .reg .b16 l, h; mov.b32 {l, h}, %2;\n\t"
                    "cvt.f32.f16 %0, l; cvt.f32.f16 %1, h; }"
                    : "=f"(f02), "=f"(f03) : "r"(t1));
                asm("{ .reg .b16 l, h; mov.b32 {l, h}, %2;\n\t"
                    "cvt.f32.f16 %0, l; cvt.f32.f16 %1, h; }"
                    : "=f"(f10), "=f"(f11) : "r"(t2));
                asm("{ .reg .b16 l, h; mov.b32 {l, h}, %2;\n\t"
                    "cvt.f32.f16 %0, l; cvt.f32.f16 %1, h; }"
                    : "=f"(f12), "=f"(f13) : "r"(t3));
                accA = fmaf(f00, v.x, accA);
                accA = fmaf(f01, v.y, accA);
                accA = fmaf(f02, v.z, accA);
                accA = fmaf(f03, v.w, accA);
                accB = fmaf(f10, v.x, accB);
                accB = fmaf(f11, v.y, accB);
                accB = fmaf(f12, v.z, accB);
                accB = fmaf(f13, v.w, accB);
            }
#pragma unroll
            for (int off = 16; off > 0; off >>= 1) {
                accA += __shfl_xor_sync(0xFFFFFFFFu, accA, off);
                accB += __shfl_xor_sync(0xFFFFFFFFu, accB, off);
            }
            if (lane == 0) {
                const int ecol = et * 8 + eo;
                const size_t i0 = (size_t)drow0 * ENCn + ecol;
                const size_t i1 = i0 + ENCn;
                out[i0]        = accA + mask[i0];
                out[half + i0] = accA;
                out[i1]        = accB + mask[i1];
                out[half + i1] = accB;
            }
        }
        __syncthreads();
    }
}

// ---------------------------------------------------------------------------
extern "C" void kernel_launch(void* const* d_in, const int* in_sizes, int n_in,
                              void* d_out, int out_size)
{
    const float* dec  = (const float*)d_in[0];
    const float* enc  = (const float*)d_in[1];
    const float* mask = (const float*)d_in[2];
    const float* W1   = (const float*)d_in[3];
    const float* W2   = (const float*)d_in[4];
    const float* vt   = (const float*)d_in[5];
    float* out = (float*)d_out;

    float *enc_t_p, *dec_t_p;
    __nv_bfloat16 *insp_p, *w1t_p, *w2t_p;
    cudaGetSymbolAddress((void**)&enc_t_p, g_enc_t);
    cudaGetSymbolAddress((void**)&dec_t_p, g_dec_t);
    cudaGetSymbolAddress((void**)&insp_p, g_in_split);
    cudaGetSymbolAddress((void**)&w1t_p, g_w1t);
    cudaGetSymbolAddress((void**)&w2t_p, g_w2t);

    int nsm = 148;
    cudaDeviceGetAttribute(&nsm, cudaDevAttrMultiProcessorCount, 0);

    prep_kernel<<<NB_SPLIT + 2 * NB_WT, 256>>>(enc, dec, W1, W2, insp_p, w1t_p, w2t_p);

    cudaFuncSetAttribute(gemm_tc_mma, cudaFuncAttributeMaxDynamicSharedMemorySize, GEMM_SMEM);
    gemm_tc_mma<<<dim3(Hd / 128, MROWS / 128), 256, GEMM_SMEM>>>(
        insp_p, w1t_p, w2t_p, enc_t_p, dec_t_p);

    cudaFuncSetAttribute(score_kernel, cudaFuncAttributeMaxDynamicSharedMemorySize, SC_SMEM);
    score_kernel<<<nsm, 512, SC_SMEM>>>(enc_t_p, dec_t_p, mask, vt, out);
}